// round 1
// baseline (speedup 1.0000x reference)
#include <cuda_runtime.h>
#include <cuda_bf16.h>

// ---------------------------------------------------------------------------
// AttentionConv3D: channel attention block
//   qkv = w_qkv @ x            (per-batch GEMM 768x256 @ 256x16384)
//   qkv = dwconv3x3(qkv)       (depthwise, middle depth slice of w_dw)
//   q,k,v split; Gram G[c,d] = sum_n q[c,n]k[d,n]; norms; softmax -> attn
//   M = fold(w_proj, attn);  out = M @ v   (per-batch GEMM 256x256 @ 256x16384)
// ---------------------------------------------------------------------------

#define BATCH 8
#define DIM   256
#define HEADS 8
#define CH    32            // DIM / HEADS
#define HW    16384         // 128*128
#define QKV_C 768           // 3*DIM

// scratch (device globals; no runtime allocation allowed)
__device__ float g_qkv [BATCH * QKV_C * HW];   // 402 MB
__device__ float g_qkvd[BATCH * QKV_C * HW];   // 402 MB
#define GRAM_CHUNKS 16
__device__ float g_gramp[GRAM_CHUNKS * BATCH * HEADS * CH * CH]; // 4 MB partials
__device__ float g_nqp  [GRAM_CHUNKS * BATCH * HEADS * CH];
__device__ float g_nkp  [GRAM_CHUNKS * BATCH * HEADS * CH];
__device__ float g_attn [BATCH * HEADS * CH * CH];
__device__ float g_M    [BATCH * DIM * DIM];

// ---------------------------------------------------------------------------
// Tiled SGEMM: C[b] = A[b] @ B[b], row-major, M%128==0 or M==256, N%128==0, K%16==0
// BM=128, BN=128, BK=16, 256 threads, 8x8 per-thread microtile.
// ---------------------------------------------------------------------------
#define BM 128
#define BN 128
#define BK 16

__global__ __launch_bounds__(256, 2)
void sgemm_kernel(const float* __restrict__ A, long long asb,
                  const float* __restrict__ B, long long bsb,
                  float* __restrict__ C, long long csb,
                  int M, int N, int K)
{
    int bz = blockIdx.z;
    A += (long long)bz * asb;
    B += (long long)bz * bsb;
    C += (long long)bz * csb;
    const int m0 = blockIdx.y * BM;
    const int n0 = blockIdx.x * BN;

    __shared__ float As[BK][BM];
    __shared__ float Bs[BK][BN];

    const int tid = threadIdx.x;
    const int ty = tid >> 4;     // 0..15
    const int tx = tid & 15;     // 0..15

    float acc[8][8];
#pragma unroll
    for (int i = 0; i < 8; i++)
#pragma unroll
        for (int j = 0; j < 8; j++) acc[i][j] = 0.f;

    for (int k0 = 0; k0 < K; k0 += BK) {
        // A tile: 128x16 floats = 512 float4, transposed store
#pragma unroll
        for (int i = 0; i < 2; i++) {
            int f  = tid + i * 256;
            int m  = f >> 2;
            int kq = (f & 3) * 4;
            float4 v = *(const float4*)(A + (long long)(m0 + m) * K + k0 + kq);
            As[kq + 0][m] = v.x;
            As[kq + 1][m] = v.y;
            As[kq + 2][m] = v.z;
            As[kq + 3][m] = v.w;
        }
        // B tile: 16x128 floats, direct copy
#pragma unroll
        for (int i = 0; i < 2; i++) {
            int f  = tid + i * 256;
            int kr = f >> 5;
            int nc = (f & 31) * 4;
            *(float4*)(&Bs[kr][nc]) =
                *(const float4*)(B + (long long)(k0 + kr) * N + n0 + nc);
        }
        __syncthreads();

#pragma unroll
        for (int kk = 0; kk < BK; kk++) {
            float a[8], bb[8];
            *(float4*)(a)      = *(const float4*)(&As[kk][ty * 8]);
            *(float4*)(a + 4)  = *(const float4*)(&As[kk][ty * 8 + 4]);
            *(float4*)(bb)     = *(const float4*)(&Bs[kk][tx * 8]);
            *(float4*)(bb + 4) = *(const float4*)(&Bs[kk][tx * 8 + 4]);
#pragma unroll
            for (int i = 0; i < 8; i++)
#pragma unroll
                for (int j = 0; j < 8; j++)
                    acc[i][j] += a[i] * bb[j];
        }
        __syncthreads();
    }

#pragma unroll
    for (int i = 0; i < 8; i++) {
        float* crow = C + (long long)(m0 + ty * 8 + i) * N + n0 + tx * 8;
        *(float4*)(crow)     = *(float4*)(&acc[i][0]);
        *(float4*)(crow + 4) = *(float4*)(&acc[i][4]);
    }
}

// ---------------------------------------------------------------------------
// Depthwise 3x3 conv, SAME (zero pad), weight = w_dw[o,0,1,:,:]
// grid: (HW/256, 768, 8)
// ---------------------------------------------------------------------------
__global__ void dwconv_kernel(const float* __restrict__ in,
                              const float* __restrict__ wdw,
                              float* __restrict__ out)
{
    const int o = blockIdx.y;
    const int b = blockIdx.z;
    __shared__ float w[9];
    if (threadIdx.x < 9) w[threadIdx.x] = wdw[o * 27 + 9 + threadIdx.x];
    __syncthreads();

    const int p = blockIdx.x * 256 + threadIdx.x;
    const int y = p >> 7, x = p & 127;
    const float* ip = in + (long long)(b * QKV_C + o) * HW;

    float acc = 0.f;
#pragma unroll
    for (int dy = -1; dy <= 1; dy++) {
        int yy = y + dy;
        if (yy < 0 || yy > 127) continue;
#pragma unroll
        for (int dx = -1; dx <= 1; dx++) {
            int xx = x + dx;
            if (xx < 0 || xx > 127) continue;
            acc += w[(dy + 1) * 3 + (dx + 1)] * __ldg(ip + yy * 128 + xx);
        }
    }
    out[(long long)(b * QKV_C + o) * HW + p] = acc;
}

// ---------------------------------------------------------------------------
// Gram partials: per (chunk, head, batch) compute 32x32 G += q@k^T over the
// chunk, plus per-row sum-of-squares for q and k. Deterministic (no atomics).
// grid: (GRAM_CHUNKS, HEADS, BATCH), 256 threads
// ---------------------------------------------------------------------------
__global__ void gram_kernel(const float* __restrict__ qkvd,
                            float* __restrict__ Gp,
                            float* __restrict__ NQp,
                            float* __restrict__ NKp)
{
    const int chunk = blockIdx.x;
    const int h = blockIdx.y;
    const int b = blockIdx.z;
    const int CHN = HW / GRAM_CHUNKS; // 1024
    const int n0 = chunk * CHN;

    const float* qbase = qkvd + (long long)(b * QKV_C + h * CH) * HW;
    const float* kbase = qkvd + (long long)(b * QKV_C + DIM + h * CH) * HW;

    __shared__ float qs[32][65];
    __shared__ float ks[32][65];

    const int tid = threadIdx.x;
    const int cc = tid >> 3;          // 0..31 : gram row
    const int d0 = (tid & 7) * 4;     // gram col base
    const int nr = tid >> 2;          // 0..63 : norm row (q rows 0..31, k rows 32..63)
    const int nt0 = (tid & 3) * 16;

    float acc0 = 0.f, acc1 = 0.f, acc2 = 0.f, acc3 = 0.f;
    float nacc = 0.f;

    for (int t0 = 0; t0 < CHN; t0 += 64) {
#pragma unroll
        for (int i = 0; i < 8; i++) {
            int lin = tid + i * 256;
            int c = lin >> 6, t = lin & 63;
            qs[c][t] = qbase[(long long)c * HW + n0 + t0 + t];
            ks[c][t] = kbase[(long long)c * HW + n0 + t0 + t];
        }
        __syncthreads();

#pragma unroll 8
        for (int t = 0; t < 64; t++) {
            float qv = qs[cc][t];
            acc0 += qv * ks[d0 + 0][t];
            acc1 += qv * ks[d0 + 1][t];
            acc2 += qv * ks[d0 + 2][t];
            acc3 += qv * ks[d0 + 3][t];
        }
        {
            const float* srow = (nr < 32) ? qs[nr] : ks[nr - 32];
#pragma unroll
            for (int t = 0; t < 16; t++) { float v = srow[nt0 + t]; nacc += v * v; }
        }
        __syncthreads();
    }

    const int bh = b * HEADS + h;
    float* gp = Gp + (((long long)chunk * 64 + bh) * CH + cc) * CH + d0;
    gp[0] = acc0; gp[1] = acc1; gp[2] = acc2; gp[3] = acc3;

    // reduce norm partial over the 4 lanes sharing a row
    nacc += __shfl_down_sync(0xffffffff, nacc, 1);
    nacc += __shfl_down_sync(0xffffffff, nacc, 2);
    if ((tid & 3) == 0) {
        if (nr < 32) NQp[((long long)chunk * 64 + bh) * CH + nr]        = nacc;
        else         NKp[((long long)chunk * 64 + bh) * CH + (nr - 32)] = nacc;
    }
}

// ---------------------------------------------------------------------------
// Reduce partials, normalize, temperature, softmax. grid: 64 blocks of 32.
// ---------------------------------------------------------------------------
__global__ void attn_kernel(const float* __restrict__ Gp,
                            const float* __restrict__ NQp,
                            const float* __restrict__ NKp,
                            const float* __restrict__ temp,
                            float* __restrict__ A)
{
    const int bh = blockIdx.x;       // 0..63
    const int c = threadIdx.x;       // 0..31
    const int h = bh & 7;

    __shared__ float invk_s[32];

    // sum norm partials
    float nq = 0.f, nk = 0.f;
    for (int ch = 0; ch < GRAM_CHUNKS; ch++) {
        nq += NQp[((long long)ch * 64 + bh) * CH + c];
        nk += NKp[((long long)ch * 64 + bh) * CH + c];
    }
    float invq = 1.f / fmaxf(sqrtf(nq), 1e-12f);
    invk_s[c]  = 1.f / fmaxf(sqrtf(nk), 1e-12f);
    __syncwarp();

    const float t = temp[h];
    float vals[32];
    float mx = -1e30f;
#pragma unroll
    for (int d = 0; d < 32; d++) {
        float g = 0.f;
        for (int ch = 0; ch < GRAM_CHUNKS; ch++)
            g += Gp[(((long long)ch * 64 + bh) * CH + c) * CH + d];
        float v = g * invq * invk_s[d] * t;
        vals[d] = v;
        mx = fmaxf(mx, v);
    }
    float s = 0.f;
#pragma unroll
    for (int d = 0; d < 32; d++) { vals[d] = expf(vals[d] - mx); s += vals[d]; }
    float inv = 1.f / s;
    float* ap = A + (long long)bh * CH * CH + c * CH;
#pragma unroll
    for (int d = 0; d < 32; d++) ap[d] = vals[d] * inv;
}

// ---------------------------------------------------------------------------
// Fold projection: M[b,o,h*32+d] = sum_c w_proj[o,h*32+c] * attn[b,h,c,d]
// grid: (HEADS, BATCH), 256 threads (one per o)
// ---------------------------------------------------------------------------
__global__ void fold_kernel(const float* __restrict__ attn,
                            const float* __restrict__ wproj,
                            float* __restrict__ Mbuf)
{
    const int h = blockIdx.x;
    const int b = blockIdx.y;
    const int o = threadIdx.x;

    __shared__ float as[32][33];
    for (int i = threadIdx.x; i < 1024; i += 256)
        as[i >> 5][i & 31] = attn[((long long)(b * HEADS + h)) * 1024 + i];
    __syncthreads();

    float wrow[32];
#pragma unroll
    for (int c = 0; c < 32; c++) wrow[c] = wproj[o * DIM + h * CH + c];

#pragma unroll 4
    for (int d = 0; d < 32; d++) {
        float acc = 0.f;
#pragma unroll
        for (int c = 0; c < 32; c++) acc += wrow[c] * as[c][d];
        Mbuf[((long long)(b * DIM + o)) * DIM + h * CH + d] = acc;
    }
}

// ---------------------------------------------------------------------------
extern "C" void kernel_launch(void* const* d_in, const int* in_sizes, int n_in,
                              void* d_out, int out_size)
{
    const float* x      = (const float*)d_in[0];
    const float* w_qkv  = (const float*)d_in[1];
    const float* w_dw   = (const float*)d_in[2];
    const float* w_proj = (const float*)d_in[3];
    const float* temp   = (const float*)d_in[4];
    float* out = (float*)d_out;

    float *qkv, *qkvd, *Gp, *NQp, *NKp, *ATT, *Mb;
    cudaGetSymbolAddress((void**)&qkv,  g_qkv);
    cudaGetSymbolAddress((void**)&qkvd, g_qkvd);
    cudaGetSymbolAddress((void**)&Gp,   g_gramp);
    cudaGetSymbolAddress((void**)&NQp,  g_nqp);
    cudaGetSymbolAddress((void**)&NKp,  g_nkp);
    cudaGetSymbolAddress((void**)&ATT,  g_attn);
    cudaGetSymbolAddress((void**)&Mb,   g_M);

    // 1) qkv = w_qkv @ x   (A shared across batches: stride 0)
    sgemm_kernel<<<dim3(HW / BN, QKV_C / BM, BATCH), 256>>>(
        w_qkv, 0LL,
        x, (long long)DIM * HW,
        qkv, (long long)QKV_C * HW,
        QKV_C, HW, DIM);

    // 2) depthwise 3x3
    dwconv_kernel<<<dim3(HW / 256, QKV_C, BATCH), 256>>>(qkv, w_dw, qkvd);

    // 3) Gram + norm partials
    gram_kernel<<<dim3(GRAM_CHUNKS, HEADS, BATCH), 256>>>(qkvd, Gp, NQp, NKp);

    // 4) attention (reduce partials + normalize + softmax)
    attn_kernel<<<BATCH * HEADS, 32>>>(Gp, NQp, NKp, temp, ATT);

    // 5) fold w_proj through attn
    fold_kernel<<<dim3(HEADS, BATCH), 256>>>(ATT, w_proj, Mb);

    // 6) out = M @ v_dw
    sgemm_kernel<<<dim3(HW / BN, DIM / BM, BATCH), 256>>>(
        Mb, (long long)DIM * DIM,
        qkvd + (long long)2 * DIM * HW, (long long)QKV_C * HW,
        out, (long long)DIM * HW,
        DIM, HW, DIM);
}

// round 3
// speedup vs baseline: 1.5769x; 1.5769x over previous
#include <cuda_runtime.h>
#include <cuda_bf16.h>
#include <cstdint>

#define BATCH 8
#define DIM   256
#define HEADS 8
#define CH    32
#define HW    16384
#define QKV_C 768
#define GK    768          // extended K = 3*256 (bf16x3 split)
#define TM    128
#define TN    128
#define BKK   64           // K chunk per stage (bf16), 128B rows
#define NCHUNK (GK / BKK)  // 12

// ---------------- device scratch ----------------
__device__ float g_qkv [BATCH * QKV_C * HW];
__device__ float g_qkvd[BATCH * QKV_C * HW];
__device__ __nv_bfloat16 g_xT  [(long long)BATCH * HW * GK];
__device__ __nv_bfloat16 g_vT  [(long long)BATCH * HW * GK];
__device__ __nv_bfloat16 g_wext[QKV_C * GK];
__device__ __nv_bfloat16 g_mext[BATCH * DIM * GK];
#define GRAM_CHUNKS 16
__device__ float g_gramp[GRAM_CHUNKS * BATCH * HEADS * CH * CH];
__device__ float g_nqp  [GRAM_CHUNKS * BATCH * HEADS * CH];
__device__ float g_nkp  [GRAM_CHUNKS * BATCH * HEADS * CH];
__device__ float g_attn [BATCH * HEADS * CH * CH];
__device__ float g_M    [BATCH * DIM * DIM];

// ---------------- helpers ----------------
__device__ __forceinline__ uint32_t smem_u32(const void* p) {
    uint32_t a;
    asm("{ .reg .u64 t; cvta.to.shared.u64 t, %1; cvt.u32.u64 %0, t; }" : "=r"(a) : "l"(p));
    return a;
}
#define SWZ(off) ((off) ^ (((off) >> 3) & 0x70))

#define CP_ASYNC16(smaddr, gptr) \
    asm volatile("cp.async.cg.shared.global [%0], [%1], 16;" :: "r"(smaddr), "l"(gptr) : "memory")
#define CP_COMMIT() asm volatile("cp.async.commit_group;" ::: "memory")
#define CP_WAIT0()  asm volatile("cp.async.wait_group 0;" ::: "memory")
#define CP_WAIT1()  asm volatile("cp.async.wait_group 1;" ::: "memory")

#define LDSM_X4(r0, r1, r2, r3, a) \
    asm volatile("ldmatrix.sync.aligned.m8n8.x4.shared.b16 {%0,%1,%2,%3}, [%4];" \
        : "=r"(r0), "=r"(r1), "=r"(r2), "=r"(r3) : "r"(a))
#define LDSM_X2(r0, r1, a) \
    asm volatile("ldmatrix.sync.aligned.m8n8.x2.shared.b16 {%0,%1}, [%2];" \
        : "=r"(r0), "=r"(r1) : "r"(a))

#define MMA_BF16(c, a, b) \
    asm volatile("mma.sync.aligned.m16n8k16.row.col.f32.bf16.bf16.f32 " \
        "{%0,%1,%2,%3}, {%4,%5,%6,%7}, {%8,%9}, {%0,%1,%2,%3};" \
        : "+f"((c)[0]), "+f"((c)[1]), "+f"((c)[2]), "+f"((c)[3]) \
        : "r"((a)[0]), "r"((a)[1]), "r"((a)[2]), "r"((a)[3]), "r"((b)[0]), "r"((b)[1]))

// smem: stage st: A at st*16384, B at 32768 + st*16384
#define SMEM_BYTES 65536

// ---------------------------------------------------------------------------
// bf16x3 GEMM: C[b][M,N] = A_ext[b][M,GK] @ B_ext[b][N,GK]^T, fp32 accumulate.
// grid (N/128, M/128, BATCH), 256 threads (8 warps, 2x4), warp tile 64x32.
// ---------------------------------------------------------------------------
__global__ void __launch_bounds__(256)
gemm_bf16x3(const __nv_bfloat16* __restrict__ A, long long asb,
            const __nv_bfloat16* __restrict__ B, long long bsb,
            float* __restrict__ C, long long csb, int N)
{
    extern __shared__ char smem[];
    const uint32_t sb = smem_u32(smem);
    const int tid = threadIdx.x;
    const int wid = tid >> 5, lane = tid & 31;
    const int m0 = blockIdx.y * TM;
    const int n0 = blockIdx.x * TN;
    A += (long long)blockIdx.z * asb + (long long)m0 * GK;
    B += (long long)blockIdx.z * bsb + (long long)n0 * GK;
    C += (long long)blockIdx.z * csb;

    const int wm = (wid >> 2) * 64;   // warp m offset within tile
    const int wn = (wid & 3) * 32;    // warp n offset

    float acc[4][4][4];
#pragma unroll
    for (int i = 0; i < 4; i++)
#pragma unroll
        for (int j = 0; j < 4; j++)
#pragma unroll
            for (int e = 0; e < 4; e++) acc[i][j][e] = 0.f;

    // per-thread load coords (8 x 16B per stage: 4 for A, 4 for B)
    const int lr = tid >> 3;        // 0..31 base row step 32? -> use idx mapping below
    (void)lr;

    auto load_stage = [&](int kc, int st) {
        const uint32_t sa = sb + st * 16384;
        const uint32_t sbB = sb + 32768 + st * 16384;
#pragma unroll
        for (int i = 0; i < 4; i++) {
            int idx = tid + i * 256;          // 0..1023
            int r = idx >> 3, ch = (idx & 7) * 16;
            const __nv_bfloat16* gp = A + (long long)r * GK + kc * BKK + (ch >> 1);
            CP_ASYNC16(sa + SWZ(r * 128 + ch), gp);
        }
#pragma unroll
        for (int i = 0; i < 4; i++) {
            int idx = tid + i * 256;
            int r = idx >> 3, ch = (idx & 7) * 16;
            const __nv_bfloat16* gp = B + (long long)r * GK + kc * BKK + (ch >> 1);
            CP_ASYNC16(sbB + SWZ(r * 128 + ch), gp);
        }
        CP_COMMIT();
    };

    load_stage(0, 0);

    // ldmatrix per-lane address components
    const int a_row_in16 = (lane & 7) + ((lane & 8) ? 8 : 0);  // 0..15
    const int a_kbyte    = (lane & 16) ? 16 : 0;
    const int b_row_in8  = lane & 7;
    const int b_kbyte    = (lane & 8) ? 16 : 0;

    for (int kc = 0; kc < NCHUNK; kc++) {
        const int st = kc & 1;
        if (kc + 1 < NCHUNK) {
            load_stage(kc + 1, st ^ 1);
            CP_WAIT1();
        } else {
            CP_WAIT0();
        }
        __syncthreads();

        const uint32_t sa = sb + st * 16384;
        const uint32_t sbB = sb + 32768 + st * 16384;

#pragma unroll
        for (int ks = 0; ks < 4; ks++) {           // 4 k16 steps in BKK=64
            uint32_t afr[4][4], bfr[4][2];
#pragma unroll
            for (int mi = 0; mi < 4; mi++) {
                int row = wm + mi * 16 + a_row_in16;
                uint32_t addr = sa + SWZ(row * 128 + ks * 32 + a_kbyte);
                LDSM_X4(afr[mi][0], afr[mi][1], afr[mi][2], afr[mi][3], addr);
            }
#pragma unroll
            for (int nj = 0; nj < 4; nj++) {
                int row = wn + nj * 8 + b_row_in8;
                uint32_t addr = sbB + SWZ(row * 128 + ks * 32 + b_kbyte);
                LDSM_X2(bfr[nj][0], bfr[nj][1], addr);
            }
#pragma unroll
            for (int mi = 0; mi < 4; mi++)
#pragma unroll
                for (int nj = 0; nj < 4; nj++)
                    MMA_BF16(acc[mi][nj], afr[mi], bfr[nj]);
        }
        __syncthreads();
    }

    // epilogue: thread holds C[g][2q],(+1) and C[g+8][2q],(+1); g=lane>>2, q=lane&3
    const int g = lane >> 2, q = lane & 3;
#pragma unroll
    for (int mi = 0; mi < 4; mi++) {
#pragma unroll
        for (int nj = 0; nj < 4; nj++) {
            int row = m0 + wm + mi * 16 + g;
            int col = n0 + wn + nj * 8 + q * 2;
            float* p0 = C + (long long)row * N + col;
            float* p1 = C + (long long)(row + 8) * N + col;
            *(float2*)p0 = make_float2(acc[mi][nj][0], acc[mi][nj][1]);
            *(float2*)p1 = make_float2(acc[mi][nj][2], acc[mi][nj][3]);
        }
    }
}

// ---------------------------------------------------------------------------
// transpose + bf16 hi/lo split: in [C=256, HW] fp32 -> out[b][n][k] ext
// k in [0,256)=hi, [256,512)=lo, [512,768)=hi   (B layout hi|lo|hi)
// ---------------------------------------------------------------------------
__global__ void convT_kernel(const float* __restrict__ in, long long bstride_in,
                             __nv_bfloat16* __restrict__ out)
{
    const int b = blockIdx.z, c0 = blockIdx.y * 32, n0 = blockIdx.x * 64;
    __shared__ float s[32][65];
    const int t = threadIdx.x;
    {
        int c = t >> 3, nq = (t & 7) * 8;
        const float* p = in + (long long)b * bstride_in + (long long)(c0 + c) * HW + n0 + nq;
        float4 v0 = *(const float4*)p;
        float4 v1 = *(const float4*)(p + 4);
        s[c][nq + 0] = v0.x; s[c][nq + 1] = v0.y; s[c][nq + 2] = v0.z; s[c][nq + 3] = v0.w;
        s[c][nq + 4] = v1.x; s[c][nq + 5] = v1.y; s[c][nq + 6] = v1.z; s[c][nq + 7] = v1.w;
    }
    __syncthreads();
    {
        int nl = t >> 2, kq = (t & 3) * 8;
        __nv_bfloat16 hi[8], lo[8];
#pragma unroll
        for (int j = 0; j < 8; j++) {
            float v = s[kq + j][nl];
            hi[j] = __float2bfloat16(v);
            lo[j] = __float2bfloat16(v - __bfloat162float(hi[j]));
        }
        __nv_bfloat16* op = out + (long long)b * ((long long)HW * GK) + (long long)(n0 + nl) * GK + c0 + kq;
        *(uint4*)op         = *(uint4*)hi;
        *(uint4*)(op + 256) = *(uint4*)lo;
        *(uint4*)(op + 512) = *(uint4*)hi;
    }
}

// A-side split: in [M,256] fp32 -> out [M,768] bf16 layout hi|hi|lo
__global__ void convA_kernel(const float* __restrict__ in, long long bstride_in,
                             __nv_bfloat16* __restrict__ out, long long bstride_out)
{
    const int m = blockIdx.x, b = blockIdx.y, k = threadIdx.x;
    float v = in[(long long)b * bstride_in + (long long)m * 256 + k];
    __nv_bfloat16 hi = __float2bfloat16(v);
    __nv_bfloat16 lo = __float2bfloat16(v - __bfloat162float(hi));
    __nv_bfloat16* op = out + (long long)b * bstride_out + (long long)m * GK + k;
    op[0] = hi; op[256] = hi; op[512] = lo;
}

// ---------------------------------------------------------------------------
__global__ void dwconv_kernel(const float* __restrict__ in,
                              const float* __restrict__ wdw,
                              float* __restrict__ out)
{
    const int o = blockIdx.y;
    const int b = blockIdx.z;
    __shared__ float w[9];
    if (threadIdx.x < 9) w[threadIdx.x] = wdw[o * 27 + 9 + threadIdx.x];
    __syncthreads();

    const int p = blockIdx.x * 256 + threadIdx.x;
    const int y = p >> 7, x = p & 127;
    const float* ip = in + (long long)(b * QKV_C + o) * HW;

    float acc = 0.f;
#pragma unroll
    for (int dy = -1; dy <= 1; dy++) {
        int yy = y + dy;
        if (yy < 0 || yy > 127) continue;
#pragma unroll
        for (int dx = -1; dx <= 1; dx++) {
            int xx = x + dx;
            if (xx < 0 || xx > 127) continue;
            acc += w[(dy + 1) * 3 + (dx + 1)] * __ldg(ip + yy * 128 + xx);
        }
    }
    out[(long long)(b * QKV_C + o) * HW + p] = acc;
}

// ---------------------------------------------------------------------------
__global__ void gram_kernel(const float* __restrict__ qkvd,
                            float* __restrict__ Gp,
                            float* __restrict__ NQp,
                            float* __restrict__ NKp)
{
    const int chunk = blockIdx.x;
    const int h = blockIdx.y;
    const int b = blockIdx.z;
    const int CHN = HW / GRAM_CHUNKS;
    const int n0 = chunk * CHN;

    const float* qbase = qkvd + (long long)(b * QKV_C + h * CH) * HW;
    const float* kbase = qkvd + (long long)(b * QKV_C + DIM + h * CH) * HW;

    __shared__ float qs[32][65];
    __shared__ float ks[32][65];

    const int tid = threadIdx.x;
    const int cc = tid >> 3;
    const int d0 = (tid & 7) * 4;
    const int nr = tid >> 2;
    const int nt0 = (tid & 3) * 16;

    float acc0 = 0.f, acc1 = 0.f, acc2 = 0.f, acc3 = 0.f;
    float nacc = 0.f;

    for (int t0 = 0; t0 < CHN; t0 += 64) {
#pragma unroll
        for (int i = 0; i < 8; i++) {
            int lin = tid + i * 256;
            int c = lin >> 6, t = lin & 63;
            qs[c][t] = qbase[(long long)c * HW + n0 + t0 + t];
            ks[c][t] = kbase[(long long)c * HW + n0 + t0 + t];
        }
        __syncthreads();

#pragma unroll 8
        for (int t = 0; t < 64; t++) {
            float qv = qs[cc][t];
            acc0 += qv * ks[d0 + 0][t];
            acc1 += qv * ks[d0 + 1][t];
            acc2 += qv * ks[d0 + 2][t];
            acc3 += qv * ks[d0 + 3][t];
        }
        {
            const float* srow = (nr < 32) ? qs[nr] : ks[nr - 32];
#pragma unroll
            for (int t = 0; t < 16; t++) { float v = srow[nt0 + t]; nacc += v * v; }
        }
        __syncthreads();
    }

    const int bh = b * HEADS + h;
    float* gp = Gp + (((long long)chunk * 64 + bh) * CH + cc) * CH + d0;
    gp[0] = acc0; gp[1] = acc1; gp[2] = acc2; gp[3] = acc3;

    nacc += __shfl_down_sync(0xffffffff, nacc, 1);
    nacc += __shfl_down_sync(0xffffffff, nacc, 2);
    if ((tid & 3) == 0) {
        if (nr < 32) NQp[((long long)chunk * 64 + bh) * CH + nr]        = nacc;
        else         NKp[((long long)chunk * 64 + bh) * CH + (nr - 32)] = nacc;
    }
}

// ---------------------------------------------------------------------------
__global__ void attn_kernel(const float* __restrict__ Gp,
                            const float* __restrict__ NQp,
                            const float* __restrict__ NKp,
                            const float* __restrict__ temp,
                            float* __restrict__ A)
{
    const int bh = blockIdx.x;
    const int c = threadIdx.x;
    const int h = bh & 7;

    __shared__ float invk_s[32];

    float nq = 0.f, nk = 0.f;
    for (int ch = 0; ch < GRAM_CHUNKS; ch++) {
        nq += NQp[((long long)ch * 64 + bh) * CH + c];
        nk += NKp[((long long)ch * 64 + bh) * CH + c];
    }
    float invq = 1.f / fmaxf(sqrtf(nq), 1e-12f);
    invk_s[c]  = 1.f / fmaxf(sqrtf(nk), 1e-12f);
    __syncwarp();

    const float t = temp[h];
    float vals[32];
    float mx = -1e30f;
#pragma unroll
    for (int d = 0; d < 32; d++) {
        float g = 0.f;
        for (int ch = 0; ch < GRAM_CHUNKS; ch++)
            g += Gp[(((long long)ch * 64 + bh) * CH + c) * CH + d];
        float v = g * invq * invk_s[d] * t;
        vals[d] = v;
        mx = fmaxf(mx, v);
    }
    float s = 0.f;
#pragma unroll
    for (int d = 0; d < 32; d++) { vals[d] = expf(vals[d] - mx); s += vals[d]; }
    float inv = 1.f / s;
    float* ap = A + (long long)bh * CH * CH + c * CH;
#pragma unroll
    for (int d = 0; d < 32; d++) ap[d] = vals[d] * inv;
}

// ---------------------------------------------------------------------------
__global__ void fold_kernel(const float* __restrict__ attn,
                            const float* __restrict__ wproj,
                            float* __restrict__ Mbuf)
{
    const int h = blockIdx.x;
    const int b = blockIdx.y;
    const int o = threadIdx.x;

    __shared__ float as[32][33];
    for (int i = threadIdx.x; i < 1024; i += 256)
        as[i >> 5][i & 31] = attn[((long long)(b * HEADS + h)) * 1024 + i];
    __syncthreads();

    float wrow[32];
#pragma unroll
    for (int c = 0; c < 32; c++) wrow[c] = wproj[o * DIM + h * CH + c];

#pragma unroll 4
    for (int d = 0; d < 32; d++) {
        float acc = 0.f;
#pragma unroll
        for (int c = 0; c < 32; c++) acc += wrow[c] * as[c][d];
        Mbuf[((long long)(b * DIM + o)) * DIM + h * CH + d] = acc;
    }
}

// ---------------------------------------------------------------------------
extern "C" void kernel_launch(void* const* d_in, const int* in_sizes, int n_in,
                              void* d_out, int out_size)
{
    const float* x      = (const float*)d_in[0];
    const float* w_qkv  = (const float*)d_in[1];
    const float* w_dw   = (const float*)d_in[2];
    const float* w_proj = (const float*)d_in[3];
    const float* temp   = (const float*)d_in[4];
    float* out = (float*)d_out;

    float *qkv, *qkvd, *Gp, *NQp, *NKp, *ATT, *Mb;
    __nv_bfloat16 *xT, *vT, *wext, *mext;
    cudaGetSymbolAddress((void**)&qkv,  g_qkv);
    cudaGetSymbolAddress((void**)&qkvd, g_qkvd);
    cudaGetSymbolAddress((void**)&Gp,   g_gramp);
    cudaGetSymbolAddress((void**)&NQp,  g_nqp);
    cudaGetSymbolAddress((void**)&NKp,  g_nkp);
    cudaGetSymbolAddress((void**)&ATT,  g_attn);
    cudaGetSymbolAddress((void**)&Mb,   g_M);
    cudaGetSymbolAddress((void**)&xT,   g_xT);
    cudaGetSymbolAddress((void**)&vT,   g_vT);
    cudaGetSymbolAddress((void**)&wext, g_wext);
    cudaGetSymbolAddress((void**)&mext, g_mext);

    cudaFuncSetAttribute(gemm_bf16x3, cudaFuncAttributeMaxDynamicSharedMemorySize, SMEM_BYTES);

    // 1) split w_qkv -> w_ext (hi|hi|lo)
    convA_kernel<<<dim3(QKV_C, 1), 256>>>(w_qkv, 0LL, wext, 0LL);

    // 2) transpose+split x -> xT_ext (hi|lo|hi)
    convT_kernel<<<dim3(HW / 64, DIM / 32, BATCH), 256>>>(x, (long long)DIM * HW, xT);

    // 3) qkv = w_ext @ xT_ext^T   (bf16x3 HMMA)
    gemm_bf16x3<<<dim3(HW / TN, QKV_C / TM, BATCH), 256, SMEM_BYTES>>>(
        wext, 0LL, xT, (long long)HW * GK, qkv, (long long)QKV_C * HW, HW);

    // 4) depthwise 3x3
    dwconv_kernel<<<dim3(HW / 256, QKV_C, BATCH), 256>>>(qkv, w_dw, qkvd);

    // 5) Gram + norm partials (fp32, exact path)
    gram_kernel<<<dim3(GRAM_CHUNKS, HEADS, BATCH), 256>>>(qkvd, Gp, NQp, NKp);

    // 6) transpose+split v -> vT_ext
    convT_kernel<<<dim3(HW / 64, DIM / 32, BATCH), 256>>>(
        qkvd + (long long)2 * DIM * HW, (long long)QKV_C * HW, vT);

    // 7) softmax attention
    attn_kernel<<<BATCH * HEADS, 32>>>(Gp, NQp, NKp, temp, ATT);

    // 8) fold w_proj through attn
    fold_kernel<<<dim3(HEADS, BATCH), 256>>>(ATT, w_proj, Mb);

    // 9) split Mb -> Mb_ext
    convA_kernel<<<dim3(DIM, BATCH), 256>>>(Mb, (long long)DIM * DIM, mext, (long long)DIM * GK);

    // 10) out = Mb_ext @ vT_ext^T
    gemm_bf16x3<<<dim3(HW / TN, DIM / TM, BATCH), 256, SMEM_BYTES>>>(
        mext, (long long)DIM * GK, vT, (long long)HW * GK, out, (long long)DIM * HW, HW);
}

// round 4
// speedup vs baseline: 2.1229x; 1.3463x over previous
#include <cuda_runtime.h>
#include <cuda_bf16.h>
#include <cstdint>

#define BATCH 8
#define DIM   256
#define HEADS 8
#define CH    32
#define HW    16384
#define QKV_C 768
#define KS    512          // stored K per side (hi|lo)
#define TM    128
#define TN    128
#define BKK   64           // K chunk per stage (bf16), 128B rows
#define NCHUNK 12          // logical chunks: 4 AhBh + 4 AhBl + 4 AlBh

// ---------------- device scratch ----------------
__device__ float g_qkv [BATCH * QKV_C * HW];
__device__ float g_qkvd[BATCH * QKV_C * HW];
__device__ __nv_bfloat16 g_xT  [(long long)BATCH * HW * KS];
__device__ __nv_bfloat16 g_vT  [(long long)BATCH * HW * KS];
__device__ __nv_bfloat16 g_wext[QKV_C * KS];
__device__ __nv_bfloat16 g_mext[BATCH * DIM * KS];
#define GRAM_CHUNKS 16
__device__ float g_gramp[GRAM_CHUNKS * BATCH * HEADS * CH * CH];
__device__ float g_nqp  [GRAM_CHUNKS * BATCH * HEADS * CH];
__device__ float g_nkp  [GRAM_CHUNKS * BATCH * HEADS * CH];
__device__ float g_attn [BATCH * HEADS * CH * CH];
__device__ float g_M    [BATCH * DIM * DIM];

// ---------------- helpers ----------------
__device__ __forceinline__ uint32_t smem_u32(const void* p) {
    uint32_t a;
    asm("{ .reg .u64 t; cvta.to.shared.u64 t, %1; cvt.u32.u64 %0, t; }" : "=r"(a) : "l"(p));
    return a;
}
#define SWZ(off) ((off) ^ (((off) >> 3) & 0x70))

#define CP_ASYNC16(smaddr, gptr) \
    asm volatile("cp.async.cg.shared.global [%0], [%1], 16;" :: "r"(smaddr), "l"(gptr) : "memory")
#define CP_COMMIT() asm volatile("cp.async.commit_group;" ::: "memory")
#define CP_WAIT0()  asm volatile("cp.async.wait_group 0;" ::: "memory")
#define CP_WAIT1()  asm volatile("cp.async.wait_group 1;" ::: "memory")

#define LDSM_X4(r0, r1, r2, r3, a) \
    asm volatile("ldmatrix.sync.aligned.m8n8.x4.shared.b16 {%0,%1,%2,%3}, [%4];" \
        : "=r"(r0), "=r"(r1), "=r"(r2), "=r"(r3) : "r"(a))
#define LDSM_X2(r0, r1, a) \
    asm volatile("ldmatrix.sync.aligned.m8n8.x2.shared.b16 {%0,%1}, [%2];" \
        : "=r"(r0), "=r"(r1) : "r"(a))

#define MMA_BF16(c, a, b) \
    asm volatile("mma.sync.aligned.m16n8k16.row.col.f32.bf16.bf16.f32 " \
        "{%0,%1,%2,%3}, {%4,%5,%6,%7}, {%8,%9}, {%0,%1,%2,%3};" \
        : "+f"((c)[0]), "+f"((c)[1]), "+f"((c)[2]), "+f"((c)[3]) \
        : "r"((a)[0]), "r"((a)[1]), "r"((a)[2]), "r"((a)[3]), "r"((b)[0]), "r"((b)[1]))

// smem: stage st: A at st*16384, B at 32768 + st*16384
#define SMEM_BYTES 65536

// ---------------------------------------------------------------------------
// bf16x3 GEMM with dedup'd K storage (KS=512 = hi|lo):
//   C = Ah@Bh^T + Ah@Bl^T + Al@Bh^T  via 12 logical chunks remapped into KS.
// grid (M/128, N/128, BATCH)  [M fastest -> B tile L2 reuse], 256 threads.
// ---------------------------------------------------------------------------
__global__ void __launch_bounds__(256)
gemm_bf16x3(const __nv_bfloat16* __restrict__ A, long long asb,
            const __nv_bfloat16* __restrict__ B, long long bsb,
            float* __restrict__ C, long long csb, int N)
{
    extern __shared__ char smem[];
    const uint32_t sb = smem_u32(smem);
    const int tid = threadIdx.x;
    const int wid = tid >> 5, lane = tid & 31;
    const int m0 = blockIdx.x * TM;
    const int n0 = blockIdx.y * TN;
    A += (long long)blockIdx.z * asb + (long long)m0 * KS;
    B += (long long)blockIdx.z * bsb + (long long)n0 * KS;
    C += (long long)blockIdx.z * csb;

    const int wm = (wid >> 2) * 64;
    const int wn = (wid & 3) * 32;

    float acc[4][4][4];
#pragma unroll
    for (int i = 0; i < 4; i++)
#pragma unroll
        for (int j = 0; j < 4; j++)
#pragma unroll
            for (int e = 0; e < 4; e++) acc[i][j][e] = 0.f;

    auto load_stage = [&](int kc, int st) {
        const int kcA = (kc < 8) ? (kc & 3) : (kc - 4);  // hi,hi,lo
        const int kcB = (kc < 8) ? kc : (kc & 3);        // hi,lo,hi
        const uint32_t sa  = sb + st * 16384;
        const uint32_t sbB = sb + 32768 + st * 16384;
#pragma unroll
        for (int i = 0; i < 4; i++) {
            int idx = tid + i * 256;
            int r = idx >> 3, ch = (idx & 7) * 16;
            const __nv_bfloat16* gp = A + (long long)r * KS + kcA * BKK + (ch >> 1);
            CP_ASYNC16(sa + SWZ(r * 128 + ch), gp);
        }
#pragma unroll
        for (int i = 0; i < 4; i++) {
            int idx = tid + i * 256;
            int r = idx >> 3, ch = (idx & 7) * 16;
            const __nv_bfloat16* gp = B + (long long)r * KS + kcB * BKK + (ch >> 1);
            CP_ASYNC16(sbB + SWZ(r * 128 + ch), gp);
        }
        CP_COMMIT();
    };

    load_stage(0, 0);

    const int a_row_in16 = lane & 15;
    const int a_kbyte    = (lane & 16) ? 16 : 0;
    const int b_row_in8  = lane & 7;
    const int b_kbyte    = (lane & 8) ? 16 : 0;

    for (int kc = 0; kc < NCHUNK; kc++) {
        const int st = kc & 1;
        if (kc + 1 < NCHUNK) {
            load_stage(kc + 1, st ^ 1);
            CP_WAIT1();
        } else {
            CP_WAIT0();
        }
        __syncthreads();

        const uint32_t sa  = sb + st * 16384;
        const uint32_t sbB = sb + 32768 + st * 16384;

#pragma unroll
        for (int ks = 0; ks < 4; ks++) {
            uint32_t afr[4][4], bfr[4][2];
#pragma unroll
            for (int mi = 0; mi < 4; mi++) {
                int row = wm + mi * 16 + a_row_in16;
                uint32_t addr = sa + SWZ(row * 128 + ks * 32 + a_kbyte);
                LDSM_X4(afr[mi][0], afr[mi][1], afr[mi][2], afr[mi][3], addr);
            }
#pragma unroll
            for (int nj = 0; nj < 4; nj++) {
                int row = wn + nj * 8 + b_row_in8;
                uint32_t addr = sbB + SWZ(row * 128 + ks * 32 + b_kbyte);
                LDSM_X2(bfr[nj][0], bfr[nj][1], addr);
            }
#pragma unroll
            for (int mi = 0; mi < 4; mi++)
#pragma unroll
                for (int nj = 0; nj < 4; nj++)
                    MMA_BF16(acc[mi][nj], afr[mi], bfr[nj]);
        }
        __syncthreads();
    }

    const int g = lane >> 2, q = lane & 3;
#pragma unroll
    for (int mi = 0; mi < 4; mi++) {
#pragma unroll
        for (int nj = 0; nj < 4; nj++) {
            int row = m0 + wm + mi * 16 + g;
            int col = n0 + wn + nj * 8 + q * 2;
            float* p0 = C + (long long)row * N + col;
            float* p1 = C + (long long)(row + 8) * N + col;
            *(float2*)p0 = make_float2(acc[mi][nj][0], acc[mi][nj][1]);
            *(float2*)p1 = make_float2(acc[mi][nj][2], acc[mi][nj][3]);
        }
    }
}

// ---------------------------------------------------------------------------
// transpose + bf16 hi/lo split: in [C=256, HW] fp32 -> out[b][n][KS]
// hi at k, lo at k+256.
// ---------------------------------------------------------------------------
__global__ void convT_kernel(const float* __restrict__ in, long long bstride_in,
                             __nv_bfloat16* __restrict__ out)
{
    const int b = blockIdx.z, c0 = blockIdx.y * 32, n0 = blockIdx.x * 64;
    __shared__ float s[32][65];
    const int t = threadIdx.x;
    {
        int c = t >> 3, nq = (t & 7) * 8;
        const float* p = in + (long long)b * bstride_in + (long long)(c0 + c) * HW + n0 + nq;
        float4 v0 = *(const float4*)p;
        float4 v1 = *(const float4*)(p + 4);
        s[c][nq + 0] = v0.x; s[c][nq + 1] = v0.y; s[c][nq + 2] = v0.z; s[c][nq + 3] = v0.w;
        s[c][nq + 4] = v1.x; s[c][nq + 5] = v1.y; s[c][nq + 6] = v1.z; s[c][nq + 7] = v1.w;
    }
    __syncthreads();
    {
        int nl = t >> 2, kq = (t & 3) * 8;
        __nv_bfloat16 hi[8], lo[8];
#pragma unroll
        for (int j = 0; j < 8; j++) {
            float v = s[kq + j][nl];
            hi[j] = __float2bfloat16(v);
            lo[j] = __float2bfloat16(v - __bfloat162float(hi[j]));
        }
        __nv_bfloat16* op = out + (long long)b * ((long long)HW * KS) + (long long)(n0 + nl) * KS + c0 + kq;
        *(uint4*)op         = *(uint4*)hi;
        *(uint4*)(op + 256) = *(uint4*)lo;
    }
}

// A-side split: in [M,256] fp32 -> out [M,KS] bf16, hi at k, lo at k+256
__global__ void convA_kernel(const float* __restrict__ in, long long bstride_in,
                             __nv_bfloat16* __restrict__ out, long long bstride_out)
{
    const int m = blockIdx.x, b = blockIdx.y, k = threadIdx.x;
    float v = in[(long long)b * bstride_in + (long long)m * 256 + k];
    __nv_bfloat16 hi = __float2bfloat16(v);
    __nv_bfloat16 lo = __float2bfloat16(v - __bfloat162float(hi));
    __nv_bfloat16* op = out + (long long)b * bstride_out + (long long)m * KS + k;
    op[0] = hi; op[256] = lo;
}

// ---------------------------------------------------------------------------
// Depthwise 3x3, SAME. Each thread: 4 contiguous pixels (float4 out).
// grid (16, QKV_C, BATCH), 256 threads (8 rows x 32 col-segments).
// ---------------------------------------------------------------------------
__global__ void __launch_bounds__(256)
dwconv_kernel(const float* __restrict__ in,
              const float* __restrict__ wdw,
              float* __restrict__ out)
{
    const int o = blockIdx.y, b = blockIdx.z;
    const int y = blockIdx.x * 8 + (threadIdx.x >> 5);
    const int c = (threadIdx.x & 31) * 4;

    __shared__ float w[9];
    if (threadIdx.x < 9) w[threadIdx.x] = wdw[o * 27 + 9 + threadIdx.x];
    __syncthreads();

    const float* ip = in + (long long)(b * QKV_C + o) * HW;

    float row[3][6];
#pragma unroll
    for (int dy = 0; dy < 3; dy++) {
        int yy = y + dy - 1;
        if (yy < 0 || yy > 127) {
#pragma unroll
            for (int j = 0; j < 6; j++) row[dy][j] = 0.f;
        } else {
            const float* rp = ip + yy * 128;
            float4 m = *(const float4*)(rp + c);
            row[dy][0] = (c > 0)   ? __ldg(rp + c - 1) : 0.f;
            row[dy][1] = m.x; row[dy][2] = m.y; row[dy][3] = m.z; row[dy][4] = m.w;
            row[dy][5] = (c < 124) ? __ldg(rp + c + 4) : 0.f;
        }
    }

    float4 res;
    float* rf = (float*)&res;
#pragma unroll
    for (int x = 0; x < 4; x++) {
        rf[x] = w[0] * row[0][x] + w[1] * row[0][x + 1] + w[2] * row[0][x + 2]
              + w[3] * row[1][x] + w[4] * row[1][x + 1] + w[5] * row[1][x + 2]
              + w[6] * row[2][x] + w[7] * row[2][x + 1] + w[8] * row[2][x + 2];
    }
    *(float4*)(out + (long long)(b * QKV_C + o) * HW + y * 128 + c) = res;
}

// ---------------------------------------------------------------------------
__global__ void gram_kernel(const float* __restrict__ qkvd,
                            float* __restrict__ Gp,
                            float* __restrict__ NQp,
                            float* __restrict__ NKp)
{
    const int chunk = blockIdx.x;
    const int h = blockIdx.y;
    const int b = blockIdx.z;
    const int CHN = HW / GRAM_CHUNKS;
    const int n0 = chunk * CHN;

    const float* qbase = qkvd + (long long)(b * QKV_C + h * CH) * HW;
    const float* kbase = qkvd + (long long)(b * QKV_C + DIM + h * CH) * HW;

    __shared__ float qs[32][65];
    __shared__ float ks[32][65];

    const int tid = threadIdx.x;
    const int cc = tid >> 3;
    const int d0 = (tid & 7) * 4;
    const int nr = tid >> 2;
    const int nt0 = (tid & 3) * 16;

    float acc0 = 0.f, acc1 = 0.f, acc2 = 0.f, acc3 = 0.f;
    float nacc = 0.f;

    for (int t0 = 0; t0 < CHN; t0 += 64) {
#pragma unroll
        for (int i = 0; i < 8; i++) {
            int lin = tid + i * 256;
            int c = lin >> 6, t = lin & 63;
            qs[c][t] = qbase[(long long)c * HW + n0 + t0 + t];
            ks[c][t] = kbase[(long long)c * HW + n0 + t0 + t];
        }
        __syncthreads();

#pragma unroll 8
        for (int t = 0; t < 64; t++) {
            float qv = qs[cc][t];
            acc0 += qv * ks[d0 + 0][t];
            acc1 += qv * ks[d0 + 1][t];
            acc2 += qv * ks[d0 + 2][t];
            acc3 += qv * ks[d0 + 3][t];
        }
        {
            const float* srow = (nr < 32) ? qs[nr] : ks[nr - 32];
#pragma unroll
            for (int t = 0; t < 16; t++) { float v = srow[nt0 + t]; nacc += v * v; }
        }
        __syncthreads();
    }

    const int bh = b * HEADS + h;
    float* gp = Gp + (((long long)chunk * 64 + bh) * CH + cc) * CH + d0;
    gp[0] = acc0; gp[1] = acc1; gp[2] = acc2; gp[3] = acc3;

    nacc += __shfl_down_sync(0xffffffff, nacc, 1);
    nacc += __shfl_down_sync(0xffffffff, nacc, 2);
    if ((tid & 3) == 0) {
        if (nr < 32) NQp[((long long)chunk * 64 + bh) * CH + nr]        = nacc;
        else         NKp[((long long)chunk * 64 + bh) * CH + (nr - 32)] = nacc;
    }
}

// ---------------------------------------------------------------------------
__global__ void attn_kernel(const float* __restrict__ Gp,
                            const float* __restrict__ NQp,
                            const float* __restrict__ NKp,
                            const float* __restrict__ temp,
                            float* __restrict__ A)
{
    const int bh = blockIdx.x;
    const int c = threadIdx.x;
    const int h = bh & 7;

    __shared__ float invk_s[32];

    float nq = 0.f, nk = 0.f;
    for (int ch = 0; ch < GRAM_CHUNKS; ch++) {
        nq += NQp[((long long)ch * 64 + bh) * CH + c];
        nk += NKp[((long long)ch * 64 + bh) * CH + c];
    }
    float invq = 1.f / fmaxf(sqrtf(nq), 1e-12f);
    invk_s[c]  = 1.f / fmaxf(sqrtf(nk), 1e-12f);
    __syncwarp();

    const float t = temp[h];
    float vals[32];
    float mx = -1e30f;
#pragma unroll
    for (int d = 0; d < 32; d++) {
        float g = 0.f;
        for (int ch = 0; ch < GRAM_CHUNKS; ch++)
            g += Gp[(((long long)ch * 64 + bh) * CH + c) * CH + d];
        float v = g * invq * invk_s[d] * t;
        vals[d] = v;
        mx = fmaxf(mx, v);
    }
    float s = 0.f;
#pragma unroll
    for (int d = 0; d < 32; d++) { vals[d] = expf(vals[d] - mx); s += vals[d]; }
    float inv = 1.f / s;
    float* ap = A + (long long)bh * CH * CH + c * CH;
#pragma unroll
    for (int d = 0; d < 32; d++) ap[d] = vals[d] * inv;
}

// ---------------------------------------------------------------------------
__global__ void fold_kernel(const float* __restrict__ attn,
                            const float* __restrict__ wproj,
                            float* __restrict__ Mbuf)
{
    const int h = blockIdx.x;
    const int b = blockIdx.y;
    const int o = threadIdx.x;

    __shared__ float as[32][33];
    for (int i = threadIdx.x; i < 1024; i += 256)
        as[i >> 5][i & 31] = attn[((long long)(b * HEADS + h)) * 1024 + i];
    __syncthreads();

    float wrow[32];
#pragma unroll
    for (int c = 0; c < 32; c++) wrow[c] = wproj[o * DIM + h * CH + c];

#pragma unroll 4
    for (int d = 0; d < 32; d++) {
        float acc = 0.f;
#pragma unroll
        for (int c = 0; c < 32; c++) acc += wrow[c] * as[c][d];
        Mbuf[((long long)(b * DIM + o)) * DIM + h * CH + d] = acc;
    }
}

// ---------------------------------------------------------------------------
extern "C" void kernel_launch(void* const* d_in, const int* in_sizes, int n_in,
                              void* d_out, int out_size)
{
    const float* x      = (const float*)d_in[0];
    const float* w_qkv  = (const float*)d_in[1];
    const float* w_dw   = (const float*)d_in[2];
    const float* w_proj = (const float*)d_in[3];
    const float* temp   = (const float*)d_in[4];
    float* out = (float*)d_out;

    float *qkv, *qkvd, *Gp, *NQp, *NKp, *ATT, *Mb;
    __nv_bfloat16 *xT, *vT, *wext, *mext;
    cudaGetSymbolAddress((void**)&qkv,  g_qkv);
    cudaGetSymbolAddress((void**)&qkvd, g_qkvd);
    cudaGetSymbolAddress((void**)&Gp,   g_gramp);
    cudaGetSymbolAddress((void**)&NQp,  g_nqp);
    cudaGetSymbolAddress((void**)&NKp,  g_nkp);
    cudaGetSymbolAddress((void**)&ATT,  g_attn);
    cudaGetSymbolAddress((void**)&Mb,   g_M);
    cudaGetSymbolAddress((void**)&xT,   g_xT);
    cudaGetSymbolAddress((void**)&vT,   g_vT);
    cudaGetSymbolAddress((void**)&wext, g_wext);
    cudaGetSymbolAddress((void**)&mext, g_mext);

    cudaFuncSetAttribute(gemm_bf16x3, cudaFuncAttributeMaxDynamicSharedMemorySize, SMEM_BYTES);

    // 1) split w_qkv -> w_ext (hi|lo, KS=512)
    convA_kernel<<<dim3(QKV_C, 1), 256>>>(w_qkv, 0LL, wext, 0LL);

    // 2) transpose+split x -> xT (hi|lo)
    convT_kernel<<<dim3(HW / 64, DIM / 32, BATCH), 256>>>(x, (long long)DIM * HW, xT);

    // 3) qkv = bf16x3(w, x)
    gemm_bf16x3<<<dim3(QKV_C / TM, HW / TN, BATCH), 256, SMEM_BYTES>>>(
        wext, 0LL, xT, (long long)HW * KS, qkv, (long long)QKV_C * HW, HW);

    // 4) depthwise 3x3
    dwconv_kernel<<<dim3(16, QKV_C, BATCH), 256>>>(qkv, w_dw, qkvd);

    // 5) Gram + norm partials (fp32, exact path)
    gram_kernel<<<dim3(GRAM_CHUNKS, HEADS, BATCH), 256>>>(qkvd, Gp, NQp, NKp);

    // 6) transpose+split v -> vT
    convT_kernel<<<dim3(HW / 64, DIM / 32, BATCH), 256>>>(
        qkvd + (long long)2 * DIM * HW, (long long)QKV_C * HW, vT);

    // 7) softmax attention
    attn_kernel<<<BATCH * HEADS, 32>>>(Gp, NQp, NKp, temp, ATT);

    // 8) fold w_proj through attn
    fold_kernel<<<dim3(HEADS, BATCH), 256>>>(ATT, w_proj, Mb);

    // 9) split Mb -> mext
    convA_kernel<<<dim3(DIM, BATCH), 256>>>(Mb, (long long)DIM * DIM, mext, (long long)DIM * KS);

    // 10) out = bf16x3(M, v)
    gemm_bf16x3<<<dim3(DIM / TM, HW / TN, BATCH), 256, SMEM_BYTES>>>(
        mext, (long long)DIM * KS, vT, (long long)HW * KS, out, (long long)DIM * HW, HW);
}